// round 1
// baseline (speedup 1.0000x reference)
#include <cuda_runtime.h>
#include <cuda_bf16.h>
#include <math.h>

// Problem constants
#define B_     32
#define CIN    128
#define H_     112
#define W_     112
#define COUT   256
#define E_     4
#define KH     3
#define KW     3
#define HOUT   56
#define WOUT   56
#define RTAPS  (CIN*KH*KW)      // 1152
#define WPERE  (COUT*RTAPS)     // 294912

// Scratch (device globals; no runtime allocation allowed)
__device__ float g_pooled[B_ * CIN];                 // (32,128)
__device__ float g_rw[B_ * E_];                      // (32,4)
__device__ float g_Wt[E_ * RTAPS * COUT];            // experts transposed: [e][r=ic*9+t][oc]
__device__ float g_cT[(size_t)B_ * RTAPS * COUT];    // per-sample mixed:   [b][r][oc]  ~37.7MB

// ---------------------------------------------------------------------------
// 1) Global average pool: pooled[b,c] = mean(x[b,c,:,:])
// ---------------------------------------------------------------------------
__global__ __launch_bounds__(256) void pool_kernel(const float* __restrict__ x,
                                                   float* __restrict__ pooled) {
    int bc = blockIdx.x;                       // 0 .. B*CIN-1
    const float* p = x + (size_t)bc * (H_ * W_);
    float sum = 0.f;
    for (int i = threadIdx.x; i < H_ * W_; i += 256) sum += p[i];
    __shared__ float red[256];
    red[threadIdx.x] = sum;
    __syncthreads();
    for (int off = 128; off > 0; off >>= 1) {
        if (threadIdx.x < off) red[threadIdx.x] += red[threadIdx.x + off];
        __syncthreads();
    }
    if (threadIdx.x == 0) pooled[bc] = red[0] * (1.0f / (H_ * W_));
}

// ---------------------------------------------------------------------------
// 2) Routing: rw[b,e] = sigmoid(pooled[b,:] . routing_w[e,:] + routing_b[e])
// ---------------------------------------------------------------------------
__global__ void routing_kernel(const float* __restrict__ pooled,
                               const float* __restrict__ rw_w,
                               const float* __restrict__ rw_b,
                               float* __restrict__ rw) {
    int t = threadIdx.x;                       // 0..127
    int b = t >> 2, e = t & 3;
    float z = rw_b[e];
    const float* pp = pooled + b * CIN;
    const float* ww = rw_w + e * CIN;
    #pragma unroll 8
    for (int k = 0; k < CIN; k++) z = fmaf(pp[k], ww[k], z);
    rw[t] = 1.0f / (1.0f + expf(-z));
}

// ---------------------------------------------------------------------------
// 3) Transpose expert weights: Wt[e][r][oc] = W[e][oc][r]  (r = ic*9 + tap)
// ---------------------------------------------------------------------------
__global__ __launch_bounds__(256) void transpose_kernel(const float* __restrict__ w,
                                                        float* __restrict__ wt) {
    int idx = blockIdx.x * 256 + threadIdx.x;  // over E*RTAPS*COUT
    if (idx >= E_ * RTAPS * COUT) return;
    int o = idx & (COUT - 1);
    int rest = idx >> 8;                       // COUT = 256
    int r = rest % RTAPS;
    int e = rest / RTAPS;
    wt[idx] = w[((size_t)e * COUT + o) * RTAPS + r];
}

// ---------------------------------------------------------------------------
// 4) Combine: cT[b][r][oc] = sum_e rw[b,e] * Wt[e][r][oc]   (float4 vectorized)
// ---------------------------------------------------------------------------
__global__ __launch_bounds__(256) void combine_kernel(const float* __restrict__ wt,
                                                      const float* __restrict__ rw,
                                                      float* __restrict__ ct) {
    const int N4 = RTAPS * COUT / 4;           // 73728
    int b = blockIdx.y;
    int idx = blockIdx.x * 256 + threadIdx.x;  // 0 .. N4-1
    const float4* w4 = (const float4*)wt;
    float4 r0 = w4[idx];
    float4 r1 = w4[idx + N4];
    float4 r2 = w4[idx + 2 * N4];
    float4 r3 = w4[idx + 3 * N4];
    float w0 = rw[b * 4 + 0], w1 = rw[b * 4 + 1], w2 = rw[b * 4 + 2], w3 = rw[b * 4 + 3];
    float4 o;
    o.x = r0.x * w0 + r1.x * w1 + r2.x * w2 + r3.x * w3;
    o.y = r0.y * w0 + r1.y * w1 + r2.y * w2 + r3.y * w3;
    o.z = r0.z * w0 + r1.z * w1 + r2.z * w2 + r3.z * w3;
    o.w = r0.w * w0 + r1.w * w1 + r2.w * w2 + r3.w * w3;
    ((float4*)ct)[(size_t)b * N4 + idx] = o;
}

// ---------------------------------------------------------------------------
// 5) Direct conv, fp32, stride 2, pad 1, 3x3.
//    Block: (b, 64 oc, 8x8 output tile). Threads: 256 = 16 oc-threads x 16 sp.
//    Per thread: 4 oc x 4 x-positions register tile.
//    Weight scratch layout per b: [r = ic*9+tap][oc] (oc contiguous).
// ---------------------------------------------------------------------------
#define IC_CHUNK 8
#define ISM_RS   20                          // padded row stride (17 cols used)
#define ISM_PER_IC (17 * ISM_RS)             // 340

__global__ __launch_bounds__(256) void conv_kernel(const float* __restrict__ x,
                                                   const float* __restrict__ wmix,
                                                   float* __restrict__ out) {
    __shared__ __align__(16) float ism[IC_CHUNK * ISM_PER_IC];   // 8*340 floats
    __shared__ __align__(16) float wsm[IC_CHUNK * 9 * 64];       // [i][t][64]

    int tid = threadIdx.x;
    int sx = blockIdx.x % 7, sy = blockIdx.x / 7;   // 7x7 spatial tiles
    int ocb = blockIdx.y;                           // 0..3 (64-oc tiles)
    int b = blockIdx.z;

    int oh0 = sy * 8, ow0 = sx * 8;
    int ih0 = oh0 * 2 - 1, iw0 = ow0 * 2 - 1;

    int oc_t = tid & 15;          // 16 oc-threads (each owns 4 consecutive oc)
    int s    = tid >> 4;          // 16 spatial threads
    int ohl  = s >> 1;            // output row within tile 0..7
    int xg   = s & 1;             // x-group 0/1 -> out cols xg*4 .. xg*4+3

    const float* xb = x + (size_t)b * CIN * (H_ * W_);
    const float* wb = wmix + (size_t)b * RTAPS * COUT + ocb * 64;

    float acc[4][4];
    #pragma unroll
    for (int a = 0; a < 4; a++)
        #pragma unroll
        for (int c = 0; c < 4; c++) acc[a][c] = 0.f;

    for (int ic0 = 0; ic0 < CIN; ic0 += IC_CHUNK) {
        __syncthreads();
        // --- load input tile: 8 ic x 17 x 17 (zero-padded borders) ---
        for (int e = tid; e < IC_CHUNK * 289; e += 256) {
            int i = e / 289;
            int rem = e - i * 289;
            int r = rem / 17;
            int c = rem - r * 17;
            int ih = ih0 + r, iw = iw0 + c;
            float v = 0.f;
            if (ih >= 0 && ih < H_ && iw >= 0 && iw < W_)
                v = xb[(size_t)(ic0 + i) * (H_ * W_) + ih * W_ + iw];
            ism[i * ISM_PER_IC + r * ISM_RS + c] = v;
        }
        // --- load weights: 8 ic x 9 taps x 64 oc ---
        for (int e = tid; e < IC_CHUNK * 9 * 64; e += 256) {
            int o = e & 63;
            int rt = e >> 6;                      // 0..71 == i*9 + t
            wsm[e] = wb[(size_t)(ic0 * 9 + rt) * COUT + o];
        }
        __syncthreads();

        #pragma unroll 1
        for (int i = 0; i < IC_CHUNK; i++) {
            // hoist this thread's input window: 3 rows x 9 cols
            float rv[3][9];
            const float* basep = &ism[i * ISM_PER_IC + (2 * ohl) * ISM_RS + 8 * xg];
            #pragma unroll
            for (int tr = 0; tr < 3; tr++) {
                float4 a0 = *(const float4*)(basep + tr * ISM_RS);
                float4 a1 = *(const float4*)(basep + tr * ISM_RS + 4);
                rv[tr][0] = a0.x; rv[tr][1] = a0.y; rv[tr][2] = a0.z; rv[tr][3] = a0.w;
                rv[tr][4] = a1.x; rv[tr][5] = a1.y; rv[tr][6] = a1.z; rv[tr][7] = a1.w;
                rv[tr][8] = basep[tr * ISM_RS + 8];
            }
            const float* wbase = &wsm[i * 576 + oc_t * 4];
            #pragma unroll
            for (int t = 0; t < 9; t++) {
                float4 wq = *(const float4*)(wbase + t * 64);
                int tr = t / 3, tc = t - tr * 3;
                #pragma unroll
                for (int xx = 0; xx < 4; xx++) {
                    float inv = rv[tr][2 * xx + tc];
                    acc[0][xx] = fmaf(wq.x, inv, acc[0][xx]);
                    acc[1][xx] = fmaf(wq.y, inv, acc[1][xx]);
                    acc[2][xx] = fmaf(wq.z, inv, acc[2][xx]);
                    acc[3][xx] = fmaf(wq.w, inv, acc[3][xx]);
                }
            }
        }
    }

    // --- write 4 oc x 4 consecutive x positions (float4 stores) ---
    int oh = oh0 + ohl;
    int owb = ow0 + xg * 4;
    size_t obase = (((size_t)b * COUT + ocb * 64 + oc_t * 4) * HOUT + oh) * WOUT + owb;
    #pragma unroll
    for (int j = 0; j < 4; j++) {
        float4 v = make_float4(acc[j][0], acc[j][1], acc[j][2], acc[j][3]);
        *(float4*)(&out[obase + (size_t)j * (HOUT * WOUT)]) = v;
    }
}

// ---------------------------------------------------------------------------
extern "C" void kernel_launch(void* const* d_in, const int* in_sizes, int n_in,
                              void* d_out, int out_size) {
    const float* x    = (const float*)d_in[0];   // (32,128,112,112)
    const float* rw_w = (const float*)d_in[1];   // (4,128)
    const float* rw_b = (const float*)d_in[2];   // (4,)
    const float* ew   = (const float*)d_in[3];   // (4,256,128,3,3)
    float* out = (float*)d_out;                  // (32,256,56,56)

    float *pooled, *rw, *wt, *ct;
    cudaGetSymbolAddress((void**)&pooled, g_pooled);
    cudaGetSymbolAddress((void**)&rw,     g_rw);
    cudaGetSymbolAddress((void**)&wt,     g_Wt);
    cudaGetSymbolAddress((void**)&ct,     g_cT);

    pool_kernel<<<B_ * CIN, 256>>>(x, pooled);
    routing_kernel<<<1, B_ * E_>>>(pooled, rw_w, rw_b, rw);
    transpose_kernel<<<(E_ * RTAPS * COUT + 255) / 256, 256>>>(ew, wt);
    combine_kernel<<<dim3(RTAPS * COUT / 4 / 256, B_), 256>>>(wt, rw, ct);
    conv_kernel<<<dim3(49, COUT / 64, B_), 256>>>(x, ct, out);
}

// round 3
// speedup vs baseline: 6.3744x; 6.3744x over previous
#include <cuda_runtime.h>
#include <cuda_fp16.h>
#include <cstdint>
#include <math.h>

#define B_     32
#define CIN    128
#define H_     112
#define W_     112
#define COUT   256
#define E_     4
#define HOUT   56
#define WOUT   56
#define RTAPS  (CIN*9)          // 1152

// ---------------- scratch (device globals) ----------------
__device__ __align__(256) float  g_pooled[B_ * CIN];
__device__ __align__(256) float  g_rw[B_ * E_];
__device__ __align__(256) float  g_rowsum[(size_t)B_ * H_ * CIN];
__device__ __align__(256) __half g_xh[(size_t)B_ * H_ * W_ * CIN];   // NHWC fp16
__device__ __align__(256) __half g_wh[(size_t)B_ * COUT * RTAPS];    // [b][oc][t*128+ic]

// ---------------- PTX helpers ----------------
__device__ __forceinline__ uint32_t smem_u32(const void* p) {
    uint32_t a;
    asm("{ .reg .u64 t; cvta.to.shared.u64 t, %1; cvt.u32.u64 %0, t; }" : "=r"(a) : "l"(p));
    return a;
}
#define CPASYNC(dst, src, sz) \
    asm volatile("cp.async.cg.shared.global [%0], [%1], 16, %2;" \
                 :: "r"(dst), "l"(src), "r"(sz) : "memory")
#define CPCOMMIT() asm volatile("cp.async.commit_group;" ::: "memory")
#define CPWAIT1()  asm volatile("cp.async.wait_group 1;" ::: "memory")
#define CPWAIT0()  asm volatile("cp.async.wait_group 0;" ::: "memory")

#define LDSM_X4(r0, r1, r2, r3, addr) \
    asm volatile("ldmatrix.sync.aligned.m8n8.x4.shared.b16 {%0,%1,%2,%3}, [%4];" \
                 : "=r"(r0), "=r"(r1), "=r"(r2), "=r"(r3) : "r"(addr))
#define LDSM_X2(r0, r1, addr) \
    asm volatile("ldmatrix.sync.aligned.m8n8.x2.shared.b16 {%0,%1}, [%2];" \
                 : "=r"(r0), "=r"(r1) : "r"(addr))

#define MMA16816(d, a, b0, b1) \
    asm volatile("mma.sync.aligned.m16n8k16.row.col.f32.f16.f16.f32 " \
                 "{%0,%1,%2,%3}, {%4,%5,%6,%7}, {%8,%9}, {%0,%1,%2,%3};" \
                 : "+f"((d)[0]), "+f"((d)[1]), "+f"((d)[2]), "+f"((d)[3]) \
                 : "r"((a)[0]), "r"((a)[1]), "r"((a)[2]), "r"((a)[3]), \
                   "r"(b0), "r"(b1))

__device__ __forceinline__ uint32_t sw128(uint32_t off) {
    return off ^ ((off >> 3) & 0x70);
}

// ---------------------------------------------------------------------------
// 1) NCHW fp32 -> NHWC fp16, fused per-row partial pooling sums.
// ---------------------------------------------------------------------------
__global__ __launch_bounds__(256) void split_x_kernel(const float* __restrict__ x,
                                                      __half* __restrict__ xh,
                                                      float* __restrict__ rowsum) {
    __shared__ float tile[64][113];
    int tid = threadIdx.x;
    int bh = blockIdx.x;
    int b = bh / H_, ih = bh % H_;

    for (int half = 0; half < 2; half++) {
        int ic0 = half * 64;
        __syncthreads();
        const float* src = x + (((size_t)b * CIN + ic0) * H_ + ih) * W_;
        for (int idx = tid; idx < 64 * W_; idx += 256) {
            int ic = idx / W_, iw = idx % W_;
            tile[ic][iw] = src[(size_t)ic * (H_ * W_) + iw];
        }
        __syncthreads();
        if (tid < 64) {
            float s = 0.f;
            for (int iw = 0; iw < W_; iw++) s += tile[tid][iw];
            rowsum[((size_t)b * H_ + ih) * CIN + ic0 + tid] = s;
        }
        size_t obase = (((size_t)b * H_ + ih) * W_) * CIN + ic0;
        for (int idx = tid; idx < W_ * 64; idx += 256) {
            int iw = idx >> 6, ic = idx & 63;
            xh[obase + (size_t)iw * CIN + ic] = __float2half_rn(tile[ic][iw]);
        }
    }
}

__global__ void pool_reduce_kernel(const float* __restrict__ rowsum,
                                   float* __restrict__ pooled) {
    int b = blockIdx.x, ic = threadIdx.x;
    float s = 0.f;
    for (int ih = 0; ih < H_; ih++) s += rowsum[((size_t)b * H_ + ih) * CIN + ic];
    pooled[b * CIN + ic] = s * (1.0f / (H_ * W_));
}

__global__ void routing_kernel(const float* __restrict__ pooled,
                               const float* __restrict__ rw_w,
                               const float* __restrict__ rw_b,
                               float* __restrict__ rw) {
    int t = threadIdx.x;
    int b = t >> 2, e = t & 3;
    float z = rw_b[e];
    const float* pp = pooled + b * CIN;
    const float* ww = rw_w + e * CIN;
    #pragma unroll 8
    for (int k = 0; k < CIN; k++) z = fmaf(pp[k], ww[k], z);
    rw[t] = 1.0f / (1.0f + expf(-z));
}

// ---------------------------------------------------------------------------
// 2) Mix expert weights -> per-sample fp16, layout [b][oc][t*128+ic]
// ---------------------------------------------------------------------------
__global__ __launch_bounds__(256) void combine_kernel(const float* __restrict__ ew,
                                                      const float* __restrict__ rw,
                                                      __half* __restrict__ wh) {
    int idx = blockIdx.x * 256 + threadIdx.x;    // over 32*256*128
    int ic = idx & 127;
    int oc = (idx >> 7) & 255;
    int b = idx >> 15;
    float acc[9];
    #pragma unroll
    for (int t = 0; t < 9; t++) acc[t] = 0.f;
    #pragma unroll
    for (int e = 0; e < E_; e++) {
        float re = rw[b * 4 + e];
        const float* p = ew + (((size_t)e * COUT + oc) * CIN + ic) * 9;
        #pragma unroll
        for (int t = 0; t < 9; t++) acc[t] = fmaf(re, p[t], acc[t]);
    }
    size_t ob = ((size_t)b * COUT + oc) * RTAPS + ic;
    #pragma unroll
    for (int t = 0; t < 9; t++)
        wh[ob + (size_t)t * 128] = __float2half_rn(acc[t]);
}

// ---------------------------------------------------------------------------
// 3) Implicit-GEMM conv via mma.sync (fp16 in, fp32 accum).
//    Block: (b, 128 oc, 2 output rows -> N=112). BK=64, double-buffered smem.
//    8 warps: wm = wid&3 (32 oc each), wn = wid>>2 (one output row each).
// ---------------------------------------------------------------------------
#define STAGE_BYTES 30720          // A: 128x64 fp16 = 16384, B: 112x64 fp16 = 14336
#define SM_TOTAL    (2 * STAGE_BYTES)

__device__ __forceinline__ void load_chunk(int c, uint32_t smb, int stage,
                                           const __half* __restrict__ wbase,
                                           const __half* __restrict__ xb,
                                           int oh0, int tid) {
    int t = c >> 1, h = c & 1;
    int dy = t / 3, dx = t - 3 * dy;
    uint32_t sa = smb + stage * STAGE_BYTES;
    uint32_t sb = sa + 16384;

    // A: 128 rows (oc) x 64 k (ic within tap), 128B/row, SW128
    const __half* wp = wbase + t * 128 + h * 64;
    #pragma unroll
    for (int rep = 0; rep < 4; rep++) {
        int idx = tid + rep * 256;
        int row = idx >> 3, seg = idx & 7;
        const char* src = (const char*)(wp + (size_t)row * RTAPS) + seg * 16;
        CPASYNC(sa + sw128((uint32_t)(idx * 16)), src, 16);
    }
    // B: 112 rows (positions) x 64 k (ic), zero-filled OOB
    #pragma unroll
    for (int rep = 0; rep < 4; rep++) {
        int idx = tid + rep * 256;
        if (idx < 896) {
            int n = idx >> 3, seg = idx & 7;
            int p = (n >= 56) ? 1 : 0;
            int ow = n - 56 * p;
            int ih = 2 * (oh0 + p) - 1 + dy;
            int iw = 2 * ow - 1 + dx;
            bool ok = ((unsigned)ih < (unsigned)H_) && ((unsigned)iw < (unsigned)W_);
            const char* src = ok
                ? (const char*)(xb + ((size_t)ih * W_ + iw) * CIN + h * 64) + seg * 16
                : (const char*)xb;
            CPASYNC(sb + sw128((uint32_t)(idx * 16)), src, ok ? 16u : 0u);
        }
    }
}

__global__ __launch_bounds__(256) void conv_mma_kernel(const __half* __restrict__ xh,
                                                       const __half* __restrict__ wgt,
                                                       float* __restrict__ out) {
    extern __shared__ char sm[];
    uint32_t smb = smem_u32(sm);
    int tid = threadIdx.x, lane = tid & 31, wid = tid >> 5;
    int wm = wid & 3, wn = wid >> 2;
    int oh0 = blockIdx.x * 2;
    int ocb = blockIdx.y, b = blockIdx.z;

    const __half* wbase = wgt + ((size_t)b * COUT + ocb * 128) * RTAPS;
    const __half* xb = xh + (size_t)b * (H_ * W_) * CIN;

    float acc[2][7][4];
    #pragma unroll
    for (int mt = 0; mt < 2; mt++)
        #pragma unroll
        for (int nt = 0; nt < 7; nt++)
            #pragma unroll
            for (int q = 0; q < 4; q++) acc[mt][nt][q] = 0.f;

    load_chunk(0, smb, 0, wbase, xb, oh0, tid);
    CPCOMMIT();

    for (int c = 0; c < 18; c++) {
        if (c < 17) {
            load_chunk(c + 1, smb, (c + 1) & 1, wbase, xb, oh0, tid);
            CPCOMMIT();
            CPWAIT1();
        } else {
            CPWAIT0();
        }
        __syncthreads();

        uint32_t sa = smb + (c & 1) * STAGE_BYTES;
        uint32_t sb = sa + 16384;

        #pragma unroll
        for (int ks = 0; ks < 4; ks++) {
            int k0 = ks * 16;
            // A fragments: 2 m16 tiles
            uint32_t afr[2][4];
            #pragma unroll
            for (int mt = 0; mt < 2; mt++) {
                int row = wm * 32 + mt * 16 + (lane & 15);
                int kk = k0 + ((lane >> 4) << 3);
                LDSM_X4(afr[mt][0], afr[mt][1], afr[mt][2], afr[mt][3],
                        sa + sw128((uint32_t)(row * 128 + kk * 2)));
            }
            // B fragments: 7 n8 tiles (3 x4 + 1 x2)
            uint32_t bfr[7][2];
            #pragma unroll
            for (int j = 0; j < 3; j++) {
                int n = wn * 56 + j * 16 + (lane & 7) + ((lane >> 4) << 3);
                int kk = k0 + (((lane >> 3) & 1) << 3);
                LDSM_X4(bfr[2 * j][0], bfr[2 * j][1], bfr[2 * j + 1][0], bfr[2 * j + 1][1],
                        sb + sw128((uint32_t)(n * 128 + kk * 2)));
            }
            {
                int n = wn * 56 + 48 + (lane & 7);
                int kk = k0 + (((lane >> 3) & 1) << 3);
                LDSM_X2(bfr[6][0], bfr[6][1],
                        sb + sw128((uint32_t)(n * 128 + kk * 2)));
            }
            #pragma unroll
            for (int mt = 0; mt < 2; mt++)
                #pragma unroll
                for (int nt = 0; nt < 7; nt++)
                    MMA16816(acc[mt][nt], afr[mt], bfr[nt][0], bfr[nt][1]);
        }
        __syncthreads();
    }

    // ---- epilogue: each warp writes one output row (56 cols) x 32 oc ----
    int r = lane >> 2;
    int cb = (lane & 3) * 2;
    int oh = oh0 + wn;
    #pragma unroll
    for (int mt = 0; mt < 2; mt++) {
        int oc = ocb * 128 + wm * 32 + mt * 16 + r;
        #pragma unroll
        for (int nt = 0; nt < 7; nt++) {
            int ow = nt * 8 + cb;
            float* op = out + (((size_t)b * COUT + oc) * HOUT + oh) * WOUT + ow;
            float2 v0 = make_float2(acc[mt][nt][0], acc[mt][nt][1]);
            float2 v1 = make_float2(acc[mt][nt][2], acc[mt][nt][3]);
            *(float2*)op = v0;
            *(float2*)(op + (size_t)8 * HOUT * WOUT) = v1;   // oc + 8
        }
    }
}

// ---------------------------------------------------------------------------
extern "C" void kernel_launch(void* const* d_in, const int* in_sizes, int n_in,
                              void* d_out, int out_size) {
    const float* x    = (const float*)d_in[0];
    const float* rw_w = (const float*)d_in[1];
    const float* rw_b = (const float*)d_in[2];
    const float* ew   = (const float*)d_in[3];
    float* out = (float*)d_out;

    float *pooled, *rw, *rowsum;
    __half *xh, *wh;
    cudaGetSymbolAddress((void**)&pooled, g_pooled);
    cudaGetSymbolAddress((void**)&rw, g_rw);
    cudaGetSymbolAddress((void**)&rowsum, g_rowsum);
    cudaGetSymbolAddress((void**)&xh, g_xh);
    cudaGetSymbolAddress((void**)&wh, g_wh);

    split_x_kernel<<<B_ * H_, 256>>>(x, xh, rowsum);
    pool_reduce_kernel<<<B_, CIN>>>(rowsum, pooled);
    routing_kernel<<<1, B_ * E_>>>(pooled, rw_w, rw_b, rw);
    combine_kernel<<<B_ * COUT * CIN / 256, 256>>>(ew, rw, wh);

    cudaFuncSetAttribute(conv_mma_kernel,
                         cudaFuncAttributeMaxDynamicSharedMemorySize, SM_TOTAL);
    conv_mma_kernel<<<dim3(HOUT / 2, 2, B_), 256, SM_TOTAL>>>(xh, wh, out);
}